// round 10
// baseline (speedup 1.0000x reference)
#include <cuda_runtime.h>

// SpikeLoss: delta = outputs - psp(target, tau=5); loss = 0.5*sum(delta^2)
// psp: syn_t = decay*syn_{t-1} + x_t ; y_t = syn_t/tau, T=100 contiguous.
//
// Row = 100 floats = 25 float4. One warp owns 8 CONSECUTIVE rows (static
// partition: 131072 rows = 16384 warps * 8). Two batches of 4 rows; each
// batch front-issues 8 independent LDG.128 (MLP=8/warp), then runs the
// hybrid scan per row:
//   1) local serial scan of 4 elems (3 fma)
//   2) Kogge-Stone across lanes on lane totals, multiplier decay^4
//   3) exclusive carry via shfl_up, apply decay^(j+1)*carry
// Accumulate predicated on lane<25 (lanes >=25 carry nonzero scan state).

static constexpr int   T_STEPS = 100;
static constexpr int   T_VEC   = 25;          // float4 per row
static constexpr int   ROWS_PER_WARP = 8;
static constexpr float DECAY   = 0.8f;
static constexpr float INV_TAU = 0.2f;

static constexpr float D4  = 0.4096f;         // 0.8^4
static constexpr float D8  = D4 * D4;
static constexpr float D16 = D8 * D8;
static constexpr float D32 = D16 * D16;
static constexpr float D64 = D32 * D32;

__device__ __forceinline__ float row_pass(float4 tv, float4 ov, int lane, bool ok) {
    float s0 = tv.x;
    float s1 = fmaf(DECAY, s0, tv.y);
    float s2 = fmaf(DECAY, s1, tv.z);
    float s3 = fmaf(DECAY, s2, tv.w);

    float v = s3, u;
    u = __shfl_up_sync(0xffffffffu, v, 1);
    if (lane >= 1)  v = fmaf(D4,  u, v);
    u = __shfl_up_sync(0xffffffffu, v, 2);
    if (lane >= 2)  v = fmaf(D8,  u, v);
    u = __shfl_up_sync(0xffffffffu, v, 4);
    if (lane >= 4)  v = fmaf(D16, u, v);
    u = __shfl_up_sync(0xffffffffu, v, 8);
    if (lane >= 8)  v = fmaf(D32, u, v);
    u = __shfl_up_sync(0xffffffffu, v, 16);
    if (lane >= 16) v = fmaf(D64, u, v);

    float carry = __shfl_up_sync(0xffffffffu, v, 1);
    if (lane == 0) carry = 0.0f;

    s0 = fmaf(0.8f,    carry, s0);
    s1 = fmaf(0.64f,   carry, s1);
    s2 = fmaf(0.512f,  carry, s2);
    s3 = fmaf(0.4096f, carry, s3);

    float acc = 0.0f;
    if (ok) {
        float d;
        d = fmaf(-INV_TAU, s0, ov.x); acc = fmaf(d, d, acc);
        d = fmaf(-INV_TAU, s1, ov.y); acc = fmaf(d, d, acc);
        d = fmaf(-INV_TAU, s2, ov.z); acc = fmaf(d, d, acc);
        d = fmaf(-INV_TAU, s3, ov.w); acc = fmaf(d, d, acc);
    }
    return acc;
}

__global__ __launch_bounds__(256)
void spike_loss_kernel(const float* __restrict__ outputs,
                       const float* __restrict__ target,
                       float* __restrict__ out,
                       int n_rows) {
    const int lane   = threadIdx.x & 31;
    const int wid    = threadIdx.x >> 5;
    const int gwarp  = blockIdx.x * (blockDim.x >> 5) + wid;

    const bool ok = (lane < 25);
    const float4 zero4 = make_float4(0.f, 0.f, 0.f, 0.f);

    float acc = 0.0f;

    const int row0 = gwarp * ROWS_PER_WARP;

    if (row0 + ROWS_PER_WARP <= n_rows) {
        // base pointers: 8 consecutive rows = 200 consecutive float4
        const float4* __restrict__ tb =
            reinterpret_cast<const float4*>(target  + (size_t)row0 * T_STEPS);
        const float4* __restrict__ ob =
            reinterpret_cast<const float4*>(outputs + (size_t)row0 * T_STEPS);

        #pragma unroll
        for (int b = 0; b < 2; ++b) {
            const int base = b * 4 * T_VEC;   // compile-time: 0, 100
            float4 t[4], o[4];
            // front-batch 8 independent LDG.128
            #pragma unroll
            for (int r = 0; r < 4; ++r) {
                t[r] = ok ? tb[base + r * T_VEC + lane] : zero4;
                o[r] = ok ? ob[base + r * T_VEC + lane] : zero4;
            }
            #pragma unroll
            for (int r = 0; r < 4; ++r)
                acc += row_pass(t[r], o[r], lane, ok);
        }
    } else {
        // generic tail (not hit for the benchmark shape)
        for (int row = row0; row < n_rows; ++row) {
            const float4* __restrict__ tr =
                reinterpret_cast<const float4*>(target  + (size_t)row * T_STEPS);
            const float4* __restrict__ orow =
                reinterpret_cast<const float4*>(outputs + (size_t)row * T_STEPS);
            float4 t0 = ok ? tr[lane]  : zero4;
            float4 o0 = ok ? orow[lane] : zero4;
            acc += row_pass(t0, o0, lane, ok);
        }
    }

    // Warp reduction
    #pragma unroll
    for (int off = 16; off > 0; off >>= 1)
        acc += __shfl_down_sync(0xffffffffu, acc, off);

    __shared__ float warp_sums[8];
    if (lane == 0) warp_sums[wid] = acc;
    __syncthreads();

    if (wid == 0) {
        acc = (lane < (blockDim.x >> 5)) ? warp_sums[lane] : 0.0f;
        #pragma unroll
        for (int off = 4; off > 0; off >>= 1)
            acc += __shfl_down_sync(0xffffffffu, acc, off);
        if (lane == 0)
            atomicAdd(out, 0.5f * acc);
    }
}

extern "C" void kernel_launch(void* const* d_in, const int* in_sizes, int n_in,
                              void* d_out, int out_size) {
    const float* outputs = (const float*)d_in[0];
    const float* target  = (const float*)d_in[1];
    float*       out     = (float*)d_out;

    const int n_elems = in_sizes[0];
    const int n_rows  = n_elems / T_STEPS;   // 131072

    cudaMemsetAsync(out, 0, sizeof(float));

    // 2048 blocks x 8 warps = 16384 warps x 8 rows = 131072 rows exactly
    const int warps_needed  = (n_rows + ROWS_PER_WARP - 1) / ROWS_PER_WARP;
    const int blocks        = (warps_needed + 7) / 8;
    spike_loss_kernel<<<blocks, 256>>>(outputs, target, out, n_rows);
}